// round 3
// baseline (speedup 1.0000x reference)
#include <cuda_runtime.h>
#include <math_constants.h>

#define TVN 512
#define ROWS_PER_BLOCK 8
#define LAM 1.0f

// Verbatim sequential port of the JAX while_loop body from the reference
// (_tv1d_row). y: input row (immutable), x: output row. Both in shared mem.
__device__ __forceinline__ void condat_tv1d(const float* __restrict__ y,
                                            float* __restrict__ x) {
    const int n = TVN;
    const float lam = LAM;
    int k = 0, k0 = 0, km = 0, kp = 0;
    float vmin = y[0] - lam;
    float vmax = y[0] + lam;
    float umin = lam;
    float umax = -lam;

    // Safety cap: reference while_loop terminates in <= ~2n iterations.
    for (int it = 0; it < 8 * TVN; ++it) {
        bool at_end = (k == n - 1);
        float ynext = y[min(k + 1, n - 1)];

        bool neg = at_end ? (umin < 0.0f) : (ynext + umin < vmin - lam);
        bool pos = (!neg) && (at_end ? (umax > 0.0f) : (ynext + umax > vmax + lam));
        bool mid = (!neg) && (!pos);
        bool fin = mid && at_end;
        bool mneg = neg && !at_end;
        bool mpos = pos && !at_end;
        bool mmid = mid && !at_end;
        bool eneg = neg && at_end;
        bool epos = pos && at_end;

        // flush a finished segment
        float cnt_fin = (float)(k - k0 + 1);
        int hi = neg ? km : (pos ? kp : (n - 1));
        float val = pos ? vmax : (fin ? (vmin + umin / cnt_fin) : vmin);
        if (neg || pos || fin) {
            for (int i = k0; i <= hi; ++i) x[i] = val;
        }

        int nk = neg ? (km + 1) : (pos ? (kp + 1) : (k + 1));
        nk = min(nk, n - 1);
        float ynk = y[nk];

        // plain accumulation step
        float umin_t = umin + ynk - vmin;
        float umax_t = umax + ynk - vmax;
        float cnt = (float)(nk - k0 + 1);
        bool c1 = (umin_t >= lam);
        bool c2 = (umax_t <= -lam);
        float vmin_mid = c1 ? (vmin + (umin_t - lam) / cnt) : vmin;
        float umin_mid = c1 ? lam : umin_t;
        int   km_mid   = c1 ? nk : km;
        float vmax_mid = c2 ? (vmax + (umax_t + lam) / cnt) : vmax;
        float umax_mid = c2 ? (-lam) : umax_t;
        int   kp_mid   = c2 ? nk : kp;

        bool jump = neg || pos;
        int   nk0 = jump ? nk : k0;
        int   nkm = (neg || mpos) ? nk : (mmid ? km_mid : km);
        int   nkp = (pos || mneg) ? nk : (mmid ? kp_mid : kp);
        float nvmin = neg ? ynk : (mpos ? (ynk - 2.0f * lam)
                                        : (mmid ? vmin_mid : vmin));
        float nvmax = pos ? ynk : (mneg ? (ynk + 2.0f * lam)
                                        : (mmid ? vmax_mid : vmax));
        float numin = (neg || mpos) ? lam
                    : (epos ? (ynk - lam - vmin) : (mmid ? umin_mid : umin));
        float numax = (pos || mneg) ? (-lam)
                    : (eneg ? (ynk + lam - vmax) : (mmid ? umax_mid : umax));
        int nkk = fin ? k : nk;

        k = nkk; k0 = nk0; km = nkm; kp = nkp;
        vmin = nvmin; vmax = nvmax; umin = numin; umax = numax;

        if (fin) return;
    }
}

__global__ __launch_bounds__(ROWS_PER_BLOCK * 32)
void Fusedmax_74019466379623_kernel(const float* __restrict__ in,
                                    float* __restrict__ out, int nrows) {
    __shared__ float ybuf[ROWS_PER_BLOCK][TVN];
    __shared__ float zbuf[ROWS_PER_BLOCK][TVN];

    const int tid  = threadIdx.x;
    const int warp = tid >> 5;
    const int lane = tid & 31;
    const int row0 = blockIdx.x * ROWS_PER_BLOCK;

    // Cooperative coalesced load of 8 rows into shared memory.
    for (int i = tid; i < ROWS_PER_BLOCK * TVN; i += ROWS_PER_BLOCK * 32) {
        int r = i >> 9;           // TVN = 512
        int c = i & (TVN - 1);
        float v = 0.0f;
        if (row0 + r < nrows) v = in[(size_t)(row0 + r) * TVN + (size_t)c];
        ybuf[r][c] = v;
    }
    __syncthreads();

    const int row = row0 + warp;
    if (row < nrows) {
        // ---- TV prox: sequential Condat on lane 0 of this row's warp ----
        if (lane == 0) condat_tv1d(&ybuf[warp][0], &zbuf[warp][0]);
        __syncwarp();

        // ---- Sparsemax via bisection on tau (whole warp, register-resident) ----
        float v[TVN / 32];
        float mx = -CUDART_INF_F;
        #pragma unroll
        for (int i = 0; i < TVN / 32; ++i) {
            v[i] = zbuf[warp][lane + 32 * i];
            mx = fmaxf(mx, v[i]);
        }
        #pragma unroll
        for (int o = 16; o; o >>= 1)
            mx = fmaxf(mx, __shfl_xor_sync(0xffffffffu, mx, o));

        // f(tau) = sum relu(v - tau) is monotone decreasing;
        // f(mx - 1) >= 1 (max element alone), f(mx) = 0 < 1.
        float lo = mx - 1.0f, hib = mx;
        #pragma unroll 1
        for (int it = 0; it < 32; ++it) {
            float m = 0.5f * (lo + hib);
            float s = 0.0f;
            #pragma unroll
            for (int i = 0; i < TVN / 32; ++i) s += fmaxf(v[i] - m, 0.0f);
            #pragma unroll
            for (int o = 16; o; o >>= 1)
                s += __shfl_xor_sync(0xffffffffu, s, o);
            if (s >= 1.0f) lo = m; else hib = m;
        }
        float tau = 0.5f * (lo + hib);

        #pragma unroll
        for (int i = 0; i < TVN / 32; ++i)
            out[(size_t)row * TVN + (size_t)(lane + 32 * i)] =
                fmaxf(v[i] - tau, 0.0f);
    }
}

extern "C" void kernel_launch(void* const* d_in, const int* in_sizes, int n_in,
                              void* d_out, int out_size) {
    const float* x = (const float*)d_in[0];
    float* out = (float*)d_out;
    int nrows = in_sizes[0] / TVN;
    int nblocks = (nrows + ROWS_PER_BLOCK - 1) / ROWS_PER_BLOCK;
    Fusedmax_74019466379623_kernel<<<nblocks, ROWS_PER_BLOCK * 32>>>(x, out, nrows);
}

// round 4
// speedup vs baseline: 1.8138x; 1.8138x over previous
#include <cuda_runtime.h>
#include <math_constants.h>

#define TVN 512
#define LAM 1.0f
#define K1_ROWS 16          // rows per warp (lanes 0..15 active)
#define YSTRIDE 513         // 513 % 32 == 1 -> conflict-free per-lane rows
#define K2_ROWS 8           // rows per block in sparsemax kernel

// ---------------- Kernel 1: Condat TV1D, one row per lane ----------------
__global__ __launch_bounds__(32)
void Fusedmax_tv_kernel(const float* __restrict__ in,
                        float* __restrict__ out, int nrows) {
    __shared__ float ybuf[K1_ROWS * YSTRIDE];

    const int lane = threadIdx.x;
    const int row0 = blockIdx.x * K1_ROWS;

    // Cooperative coalesced load: 16 rows x 512 floats via float4.
    for (int i = lane; i < K1_ROWS * (TVN / 4); i += 32) {
        int r  = i / (TVN / 4);
        int c4 = i % (TVN / 4);
        int row = row0 + r;
        float4 v = make_float4(0.f, 0.f, 0.f, 0.f);
        if (row < nrows)
            v = ((const float4*)(in + (size_t)row * TVN))[c4];
        float* dst = ybuf + r * YSTRIDE + c4 * 4;
        dst[0] = v.x; dst[1] = v.y; dst[2] = v.z; dst[3] = v.w;
    }
    __syncwarp();

    const int myrow = row0 + lane;
    const bool act  = (lane < K1_ROWS) && (myrow < nrows);
    const float* y  = ybuf + (act ? lane : 0) * YSTRIDE;
    float* x        = out + (size_t)(act ? myrow : 0) * TVN;

    const int   n   = TVN;
    const float lam = LAM;
    int k = 0, k0 = 0, km = 0, kp = 0;
    float vmin = y[0] - lam;
    float vmax = y[0] + lam;
    float umin = lam;
    float umax = -lam;
    bool done = !act;

    // Warp-synchronous predicated Condat loop: identical math to the
    // reference while_loop; runs until every lane's row is finished.
    while (__ballot_sync(0xffffffffu, !done)) {
        if (!done) {
            bool at_end = (k == n - 1);
            float ynext = y[min(k + 1, n - 1)];

            bool neg = at_end ? (umin < 0.0f) : (ynext + umin < vmin - lam);
            bool pos = (!neg) && (at_end ? (umax > 0.0f)
                                         : (ynext + umax > vmax + lam));
            bool mid  = (!neg) && (!pos);
            bool fin  = mid && at_end;
            bool mneg = neg && !at_end;
            bool mpos = pos && !at_end;
            bool mmid = mid && !at_end;
            bool eneg = neg && at_end;
            bool epos = pos && at_end;

            // flush a finished segment directly to global memory
            float cnt_fin = (float)(k - k0 + 1);
            int hi   = neg ? km : (pos ? kp : (n - 1));
            float val = pos ? vmax : (fin ? (vmin + umin / cnt_fin) : vmin);
            if (neg || pos || fin) {
                for (int i = k0; i <= hi; ++i) x[i] = val;
            }

            if (fin) {
                done = true;
            } else {
                int nk = neg ? (km + 1) : (pos ? (kp + 1) : (k + 1));
                nk = min(nk, n - 1);
                float ynk = y[nk];

                float umin_t = umin + ynk - vmin;
                float umax_t = umax + ynk - vmax;
                float cnt = (float)(nk - k0 + 1);
                bool c1 = (umin_t >= lam);
                bool c2 = (umax_t <= -lam);
                float vmin_mid = c1 ? (vmin + (umin_t - lam) / cnt) : vmin;
                float umin_mid = c1 ? lam : umin_t;
                int   km_mid   = c1 ? nk : km;
                float vmax_mid = c2 ? (vmax + (umax_t + lam) / cnt) : vmax;
                float umax_mid = c2 ? (-lam) : umax_t;
                int   kp_mid   = c2 ? nk : kp;

                bool jump = neg || pos;
                int   nk0 = jump ? nk : k0;
                int   nkm = (neg || mpos) ? nk : (mmid ? km_mid : km);
                int   nkp = (pos || mneg) ? nk : (mmid ? kp_mid : kp);
                float nvmin = neg ? ynk : (mpos ? (ynk - 2.0f * lam)
                                                : (mmid ? vmin_mid : vmin));
                float nvmax = pos ? ynk : (mneg ? (ynk + 2.0f * lam)
                                                : (mmid ? vmax_mid : vmax));
                float numin = (neg || mpos) ? lam
                            : (epos ? (ynk - lam - vmin)
                                    : (mmid ? umin_mid : umin));
                float numax = (pos || mneg) ? (-lam)
                            : (eneg ? (ynk + lam - vmax)
                                    : (mmid ? umax_mid : umax));

                k = nk; k0 = nk0; km = nkm; kp = nkp;
                vmin = nvmin; vmax = nvmax; umin = numin; umax = numax;
            }
        }
    }
}

// ---------------- Kernel 2: sparsemax in place, warp per row ----------------
__global__ __launch_bounds__(K2_ROWS * 32)
void Fusedmax_sparsemax_kernel(float* __restrict__ out, int nrows) {
    const int tid  = threadIdx.x;
    const int warp = tid >> 5;
    const int lane = tid & 31;
    const int row  = blockIdx.x * K2_ROWS + warp;
    if (row >= nrows) return;

    float* z = out + (size_t)row * TVN;

    float v[TVN / 32];
    float mx = -CUDART_INF_F;
    #pragma unroll
    for (int i = 0; i < TVN / 32; ++i) {
        v[i] = z[lane + 32 * i];
        mx = fmaxf(mx, v[i]);
    }
    #pragma unroll
    for (int o = 16; o; o >>= 1)
        mx = fmaxf(mx, __shfl_xor_sync(0xffffffffu, mx, o));

    // f(tau) = sum relu(v - tau): f(mx-1) >= 1, f(mx) = 0. Bisect.
    float lo = mx - 1.0f, hib = mx;
    #pragma unroll 1
    for (int it = 0; it < 32; ++it) {
        float m = 0.5f * (lo + hib);
        float s = 0.0f;
        #pragma unroll
        for (int i = 0; i < TVN / 32; ++i) s += fmaxf(v[i] - m, 0.0f);
        #pragma unroll
        for (int o = 16; o; o >>= 1)
            s += __shfl_xor_sync(0xffffffffu, s, o);
        if (s >= 1.0f) lo = m; else hib = m;
    }
    float tau = 0.5f * (lo + hib);

    #pragma unroll
    for (int i = 0; i < TVN / 32; ++i)
        z[lane + 32 * i] = fmaxf(v[i] - tau, 0.0f);
}

extern "C" void kernel_launch(void* const* d_in, const int* in_sizes, int n_in,
                              void* d_out, int out_size) {
    const float* x = (const float*)d_in[0];
    float* out = (float*)d_out;
    int nrows = in_sizes[0] / TVN;

    int g1 = (nrows + K1_ROWS - 1) / K1_ROWS;
    Fusedmax_tv_kernel<<<g1, 32>>>(x, out, nrows);

    int g2 = (nrows + K2_ROWS - 1) / K2_ROWS;
    Fusedmax_sparsemax_kernel<<<g2, K2_ROWS * 32>>>(out, nrows);
}

// round 5
// speedup vs baseline: 1.9264x; 1.0621x over previous
#include <cuda_runtime.h>
#include <math_constants.h>

#define TVN 512
#define LAM 1.0f
#define RPW 8            // rows per warp (one warp per block)
#define YS  516          // ybuf float stride: mult of 4 (float4), %32==4 (conflict-free lanes)

__global__ __launch_bounds__(32)
void Fusedmax_fused_kernel(const float* __restrict__ in,
                           float* __restrict__ out, int nrows) {
    __shared__ float          ybuf[RPW * YS];      // 16.5 KB: y, then reused for TV result
    __shared__ float          segval[RPW * 513];   // 16.4 KB: per-event segment value
    __shared__ unsigned short seghi [RPW * 514];   //  8.2 KB: per-event segment end index

    const int lane = threadIdx.x;
    const int row0 = blockIdx.x * RPW;

    // Cooperative coalesced float4 load of RPW rows.
    for (int i = lane; i < RPW * (TVN / 4); i += 32) {
        int r  = i / (TVN / 4);
        int c4 = i % (TVN / 4);
        int row = row0 + r;
        float4 v = make_float4(0.f, 0.f, 0.f, 0.f);
        if (row < nrows) v = ((const float4*)(in + (size_t)row * TVN))[c4];
        float* dst = ybuf + r * YS + c4 * 4;
        dst[0] = v.x; dst[1] = v.y; dst[2] = v.z; dst[3] = v.w;
    }
    __syncwarp();

    const bool act = (lane < RPW) && (row0 + lane < nrows);
    if (act) {
        const float*    y  = ybuf  + lane * YS;
        float*          sv = segval + lane * 513;
        unsigned short* sh = seghi  + lane * 514;

        // ---- Condat TV1D: branchless body, segment-recording (verbatim math) ----
        int cnt = 0;
        int k = 0, k0 = 0, km = 0, kp = 0;
        float vmin = y[0] - LAM, vmax = y[0] + LAM;
        float umin = LAM, umax = -LAM;

        for (;;) {
            bool at_end = (k == TVN - 1);
            float ynext = y[min(k + 1, TVN - 1)];

            bool neg = at_end ? (umin < 0.0f) : (ynext + umin < vmin - LAM);
            bool pos = (!neg) && (at_end ? (umax > 0.0f)
                                         : (ynext + umax > vmax + LAM));
            bool mid = (!neg) && (!pos);
            bool fin = mid && at_end;

            // record a finished segment (contiguous: start implied)
            float cnt_fin = (float)(k - k0 + 1);
            int   hi  = neg ? km : (pos ? kp : (TVN - 1));
            float val = pos ? vmax : (fin ? (vmin + umin / cnt_fin) : vmin);
            if (neg | pos | fin) {
                sv[cnt] = val;
                sh[cnt] = (unsigned short)hi;
                ++cnt;
            }
            if (fin) break;

            bool mneg = neg && !at_end;
            bool mpos = pos && !at_end;
            bool mmid = mid && !at_end;
            bool eneg = neg && at_end;
            bool epos = pos && at_end;

            int nk = neg ? (km + 1) : (pos ? (kp + 1) : (k + 1));
            nk = min(nk, TVN - 1);
            float ynk = y[nk];

            float umin_t = umin + ynk - vmin;
            float umax_t = umax + ynk - vmax;
            float c = (float)(nk - k0 + 1);
            bool c1 = (umin_t >= LAM);
            bool c2 = (umax_t <= -LAM);
            float vmin_mid = c1 ? (vmin + (umin_t - LAM) / c) : vmin;
            float umin_mid = c1 ? LAM : umin_t;
            int   km_mid   = c1 ? nk : km;
            float vmax_mid = c2 ? (vmax + (umax_t + LAM) / c) : vmax;
            float umax_mid = c2 ? (-LAM) : umax_t;
            int   kp_mid   = c2 ? nk : kp;

            bool jump = neg || pos;
            k0 = jump ? nk : k0;
            int   nkm = (neg || mpos) ? nk : (mmid ? km_mid : km);
            int   nkp = (pos || mneg) ? nk : (mmid ? kp_mid : kp);
            float nvmin = neg ? ynk : (mpos ? (ynk - 2.0f * LAM)
                                            : (mmid ? vmin_mid : vmin));
            float nvmax = pos ? ynk : (mneg ? (ynk + 2.0f * LAM)
                                            : (mmid ? vmax_mid : vmax));
            float numin = (neg || mpos) ? LAM
                        : (epos ? (ynk - LAM - vmin) : (mmid ? umin_mid : umin));
            float numax = (pos || mneg) ? (-LAM)
                        : (eneg ? (ynk + LAM - vmax) : (mmid ? umax_mid : umax));

            k = nk; km = nkm; kp = nkp;
            vmin = nvmin; vmax = nvmax; umin = numin; umax = numax;
        }

        // ---- Expand segments into ybuf (overwrite own row; uniform loop) ----
        float* xr = ybuf + lane * YS;
        int   s  = 0;
        float v0 = sv[0];
        int   h0 = sh[0];
        for (int i = 0; i < TVN; ++i) {
            if (i > h0) { ++s; v0 = sv[s]; h0 = sh[s]; }
            xr[i] = v0;
        }
    }
    __syncwarp();

    // ---- Sparsemax, warp-collective per row, written straight to output ----
    for (int r = 0; r < RPW; ++r) {
        int row = row0 + r;
        if (row >= nrows) break;
        const float* z = ybuf + r * YS;

        float v[TVN / 32];
        float mx = -CUDART_INF_F;
        #pragma unroll
        for (int i = 0; i < TVN / 32; ++i) {
            v[i] = z[lane + 32 * i];
            mx = fmaxf(mx, v[i]);
        }
        #pragma unroll
        for (int o = 16; o; o >>= 1)
            mx = fmaxf(mx, __shfl_xor_sync(0xffffffffu, mx, o));

        // f(tau) = sum relu(v - tau): f(mx-1) >= 1, f(mx) = 0. Bisect.
        float lo = mx - 1.0f, hb = mx;
        #pragma unroll 1
        for (int it = 0; it < 28; ++it) {
            float m = 0.5f * (lo + hb);
            float sum = 0.0f;
            #pragma unroll
            for (int i = 0; i < TVN / 32; ++i) sum += fmaxf(v[i] - m, 0.0f);
            #pragma unroll
            for (int o = 16; o; o >>= 1)
                sum += __shfl_xor_sync(0xffffffffu, sum, o);
            if (sum >= 1.0f) lo = m; else hb = m;
        }
        float tau = 0.5f * (lo + hb);

        #pragma unroll
        for (int i = 0; i < TVN / 32; ++i)
            out[(size_t)row * TVN + (size_t)(lane + 32 * i)] =
                fmaxf(v[i] - tau, 0.0f);
    }
}

extern "C" void kernel_launch(void* const* d_in, const int* in_sizes, int n_in,
                              void* d_out, int out_size) {
    const float* x = (const float*)d_in[0];
    float* out = (float*)d_out;
    int nrows = in_sizes[0] / TVN;
    int nblocks = (nrows + RPW - 1) / RPW;
    Fusedmax_fused_kernel<<<nblocks, 32>>>(x, out, nrows);
}

// round 8
// speedup vs baseline: 5.4997x; 2.8549x over previous
#include <cuda_runtime.h>
#include <math_constants.h>

#define TVN  512
#define LAM  1.0f
#define RPW  8            // rows per warp (lanes 0..7 run Condat)
#define YS   516          // ybuf stride: mult of 4, %32==4 -> conflict-free
#define SEGS 520          // segment buffers per row (cnt+2 <= 514 guaranteed)

__global__ __launch_bounds__(32)
void Fusedmax_fused_kernel(const float* __restrict__ in,
                           float* __restrict__ out, int nrows) {
    __shared__ float          ybuf  [RPW * YS];    // y, then TV result
    __shared__ float          segval[RPW * SEGS];
    __shared__ unsigned short seghi [RPW * SEGS];
    __shared__ float          rcp_tab[TVN + 2];    // rcp_tab[c] = 1/c

    const int lane = threadIdx.x;
    const int row0 = blockIdx.x * RPW;

    for (int i = lane; i < TVN + 2; i += 32)
        rcp_tab[i] = 1.0f / (float)max(i, 1);

    // Cooperative coalesced float4 load of RPW rows.
    for (int i = lane; i < RPW * (TVN / 4); i += 32) {
        int r  = i / (TVN / 4);
        int c4 = i % (TVN / 4);
        int row = row0 + r;
        float4 v = make_float4(0.f, 0.f, 0.f, 0.f);
        if (row < nrows) v = ((const float4*)(in + (size_t)row * TVN))[c4];
        float* dst = ybuf + r * YS + c4 * 4;
        dst[0] = v.x; dst[1] = v.y; dst[2] = v.z; dst[3] = v.w;
    }
    __syncwarp();

    const bool act = (lane < RPW) && (row0 + lane < nrows);
    if (act) {
        const float*    y  = ybuf   + lane * YS;
        float*          sv = segval + lane * SEGS;
        unsigned short* sh = seghi  + lane * SEGS;

        // ---- Condat TV1D: register-cached y window, division-free chain ----
        int cnt = 0;
        int k = 0, k0 = 0, km = 0, kp = 0;
        float vmin = y[0] - LAM, vmax = y[0] + LAM;
        float umin = LAM, umax = -LAM;
        float yn1 = y[1];    // y[min(k+1, n-1)]
        float yn2 = y[2];    // y[min(k+2, n-1)]

        for (;;) {
            // off-chain speculative table loads (indices known at iter start)
            float rc_rec = rcp_tab[k - k0 + 1];   // 1/(k-k0+1)   (fin flush)
            float rc_mid = rcp_tab[k - k0 + 2];   // 1/(nk-k0+1)  (mid advance)

            bool at_end = (k == TVN - 1);
            bool neg = at_end ? (umin < 0.0f) : (yn1 + umin < vmin - LAM);
            bool pos = (!neg) && (at_end ? (umax > 0.0f)
                                         : (yn1 + umax > vmax + LAM));
            bool mid = (!neg) && (!pos);
            bool fin = mid && at_end;

            int   hi  = neg ? km : (pos ? kp : (TVN - 1));
            float val = pos ? vmax : (fin ? (vmin + umin * rc_rec) : vmin);
            if (neg | pos | fin) {
                sv[cnt] = val;
                sh[cnt] = (unsigned short)hi;
                ++cnt;
            }
            if (fin) break;

            bool mneg = neg && !at_end;
            bool mpos = pos && !at_end;
            bool mmid = mid && !at_end;
            bool eneg = neg && at_end;
            bool epos = pos && at_end;
            bool jump = neg | pos;

            int nk = neg ? (km + 1) : (pos ? (kp + 1) : (k + 1));
            nk = min(nk, TVN - 1);

            // mid path: all three y values come from registers
            float ynk  = jump ? y[nk] : yn1;
            float nyn1 = jump ? y[min(nk + 1, TVN - 1)] : yn2;
            float nyn2 = y[min(nk + 2, TVN - 1)];   // consumed 2 iters later

            float umin_t = umin + ynk - vmin;
            float umax_t = umax + ynk - vmax;
            bool c1 = (umin_t >= LAM);
            bool c2 = (umax_t <= -LAM);
            // division-dependent values are only consumed in mmid, where
            // nk = k+1 so 1/(nk-k0+1) == rc_mid.
            float vmin_mid = c1 ? (vmin + (umin_t - LAM) * rc_mid) : vmin;
            float umin_mid = c1 ? LAM : umin_t;
            int   km_mid   = c1 ? nk : km;
            float vmax_mid = c2 ? (vmax + (umax_t + LAM) * rc_mid) : vmax;
            float umax_mid = c2 ? (-LAM) : umax_t;
            int   kp_mid   = c2 ? nk : kp;

            k0 = jump ? nk : k0;
            int   nkm = (neg || mpos) ? nk : (mmid ? km_mid : km);
            int   nkp = (pos || mneg) ? nk : (mmid ? kp_mid : kp);
            float nvmin = neg ? ynk : (mpos ? (ynk - 2.0f * LAM)
                                            : (mmid ? vmin_mid : vmin));
            float nvmax = pos ? ynk : (mneg ? (ynk + 2.0f * LAM)
                                            : (mmid ? vmax_mid : vmax));
            float numin = (neg || mpos) ? LAM
                        : (epos ? (ynk - LAM - vmin)
                                : (mmid ? umin_mid : umin));
            float numax = (pos || mneg) ? (-LAM)
                        : (eneg ? (ynk + LAM - vmax)
                                : (mmid ? umax_mid : umax));

            k = nk; km = nkm; kp = nkp;
            vmin = nvmin; vmax = nvmax; umin = numin; umax = numax;
            yn1 = nyn1; yn2 = nyn2;
        }

        // ---- Expand segments into ybuf (prefetched next-segment registers) ----
        float* xr = ybuf + lane * YS;
        int s = 0;
        float v0 = sv[0]; int h0 = sh[0];
        float v1 = sv[1]; int h1 = sh[1];
        for (int i = 0; i < TVN; ++i) {
            if (i > h0) { v0 = v1; h0 = h1; ++s; v1 = sv[s + 1]; h1 = sh[s + 1]; }
            xr[i] = v0;
        }
    }
    __syncwarp();

    // ---- Sparsemax: warp-collective bisection, two rows interleaved ----
    for (int r = 0; r < RPW; r += 2) {
        int rowA = row0 + r;
        int rowB = row0 + r + 1;
        if (rowA >= nrows) break;
        bool hasB = (rowB < nrows);
        const float* za = ybuf + r * YS;
        const float* zb = ybuf + (hasB ? (r + 1) : r) * YS;

        float va[TVN / 32], vb[TVN / 32];
        float mxa = -CUDART_INF_F, mxb = -CUDART_INF_F;
        #pragma unroll
        for (int i = 0; i < TVN / 32; ++i) {
            va[i] = za[lane + 32 * i]; mxa = fmaxf(mxa, va[i]);
            vb[i] = zb[lane + 32 * i]; mxb = fmaxf(mxb, vb[i]);
        }
        #pragma unroll
        for (int o = 16; o; o >>= 1) {
            mxa = fmaxf(mxa, __shfl_xor_sync(0xffffffffu, mxa, o));
            mxb = fmaxf(mxb, __shfl_xor_sync(0xffffffffu, mxb, o));
        }

        float loA = mxa - 1.0f, hbA = mxa;
        float loB = mxb - 1.0f, hbB = mxb;
        #pragma unroll 1
        for (int it = 0; it < 24; ++it) {
            float mA = 0.5f * (loA + hbA);
            float mB = 0.5f * (loB + hbB);
            float s0a = 0.f, s1a = 0.f, s2a = 0.f, s3a = 0.f;
            float s0b = 0.f, s1b = 0.f, s2b = 0.f, s3b = 0.f;
            #pragma unroll
            for (int i = 0; i < TVN / 32; i += 4) {
                s0a += fmaxf(va[i]     - mA, 0.f);
                s1a += fmaxf(va[i + 1] - mA, 0.f);
                s2a += fmaxf(va[i + 2] - mA, 0.f);
                s3a += fmaxf(va[i + 3] - mA, 0.f);
                s0b += fmaxf(vb[i]     - mB, 0.f);
                s1b += fmaxf(vb[i + 1] - mB, 0.f);
                s2b += fmaxf(vb[i + 2] - mB, 0.f);
                s3b += fmaxf(vb[i + 3] - mB, 0.f);
            }
            float sa = (s0a + s1a) + (s2a + s3a);
            float sb = (s0b + s1b) + (s2b + s3b);
            #pragma unroll
            for (int o = 16; o; o >>= 1) {
                sa += __shfl_xor_sync(0xffffffffu, sa, o);
                sb += __shfl_xor_sync(0xffffffffu, sb, o);
            }
            if (sa >= 1.0f) loA = mA; else hbA = mA;
            if (sb >= 1.0f) loB = mB; else hbB = mB;
        }
        float tauA = 0.5f * (loA + hbA);
        float tauB = 0.5f * (loB + hbB);

        #pragma unroll
        for (int i = 0; i < TVN / 32; ++i) {
            out[(size_t)rowA * TVN + (size_t)(lane + 32 * i)] =
                fmaxf(va[i] - tauA, 0.0f);
            if (hasB)
                out[(size_t)rowB * TVN + (size_t)(lane + 32 * i)] =
                    fmaxf(vb[i] - tauB, 0.0f);
        }
    }
}

extern "C" void kernel_launch(void* const* d_in, const int* in_sizes, int n_in,
                              void* d_out, int out_size) {
    const float* x = (const float*)d_in[0];
    float* out = (float*)d_out;
    int nrows = in_sizes[0] / TVN;
    int nblocks = (nrows + RPW - 1) / RPW;
    Fusedmax_fused_kernel<<<nblocks, 32>>>(x, out, nrows);
}

// round 12
// speedup vs baseline: 6.6425x; 1.2078x over previous
#include <cuda_runtime.h>
#include <math_constants.h>

#define TVN  512
#define LAM  1.0f
#define RPW  8            // rows per warp (lanes 0..7 run Condat)
#define YS   516          // ybuf stride: mult of 4, %32==4 -> conflict-free
#define SEGS 520          // segment buffers per row

__global__ __launch_bounds__(32)
void Fusedmax_fused_kernel(const float* __restrict__ in,
                           float* __restrict__ out, int nrows) {
    __shared__ float          ybuf  [RPW * YS];    // y, then TV result
    __shared__ float          segval[RPW * SEGS];
    __shared__ unsigned short seghi [RPW * SEGS];
    __shared__ float          rcp_tab[TVN + 2];    // rcp_tab[c] = 1/c

    const int lane = threadIdx.x;
    const int row0 = blockIdx.x * RPW;

    for (int i = lane; i < TVN + 2; i += 32)
        rcp_tab[i] = 1.0f / (float)max(i, 1);

    // Cooperative coalesced float4 load of RPW rows.
    for (int i = lane; i < RPW * (TVN / 4); i += 32) {
        int r  = i / (TVN / 4);
        int c4 = i % (TVN / 4);
        int row = row0 + r;
        float4 v = make_float4(0.f, 0.f, 0.f, 0.f);
        if (row < nrows) v = ((const float4*)(in + (size_t)row * TVN))[c4];
        float* dst = ybuf + r * YS + c4 * 4;
        dst[0] = v.x; dst[1] = v.y; dst[2] = v.z; dst[3] = v.w;
    }
    __syncwarp();

    const bool act = (lane < RPW) && (row0 + lane < nrows);
    if (act) {
        const float*    y  = ybuf   + lane * YS;
        float*          sv = segval + lane * SEGS;
        unsigned short* sh = seghi  + lane * SEGS;

        // ---- Condat TV1D: no on-chain LDS, no divergent branches in body ----
        int cnt = 0;
        int k = 0, k0 = 0, km = 0, kp = 0;
        float vmin = y[0] - LAM, vmax = y[0] + LAM;
        float umin = LAM, umax = -LAM;
        float yn1 = y[1];    // y[min(k+1, n-1)]
        float yn2 = y[2];    // y[min(k+2, n-1)]

        for (;;) {
            // All addresses below depend only on PREVIOUS-iteration registers:
            // issue these loads immediately, fully off the predicate chain.
            int ia1 = min(km + 1, TVN - 1), ia2 = min(km + 2, TVN - 1);
            int ib1 = min(kp + 1, TVN - 1), ib2 = min(kp + 2, TVN - 1);
            float yA1 = y[ia1], yA2 = y[ia2];   // neg-jump candidates
            float yB1 = y[ib1], yB2 = y[ib2];   // pos-jump candidates
            float rc_rec = rcp_tab[k - k0 + 1]; // 1/(k-k0+1)
            float rc_mid = rcp_tab[k - k0 + 2]; // 1/(nk-k0+1) for mid (nk=k+1)

            bool at_end = (k == TVN - 1);
            bool neg = at_end ? (umin < 0.0f) : (yn1 + umin < vmin - LAM);
            bool pos = (!neg) && (at_end ? (umax > 0.0f)
                                         : (yn1 + umax > vmax + LAM));
            bool mid = (!neg) && (!pos);
            bool fin = mid && at_end;
            bool ev  = neg | pos | fin;

            // Branchless segment record: always store into slot cnt,
            // advance cnt only on a real event (stale slot gets overwritten).
            int   hi  = neg ? km : (pos ? kp : (TVN - 1));
            float val = pos ? vmax : (fin ? (vmin + umin * rc_rec) : vmin);
            sv[cnt] = val;
            sh[cnt] = (unsigned short)hi;
            cnt += ev;
            if (fin) break;

            bool mneg = neg && !at_end;
            bool mpos = pos && !at_end;
            bool mmid = mid && !at_end;
            bool eneg = neg && at_end;
            bool epos = pos && at_end;
            bool jump = neg | pos;

            int nk = neg ? ia1 : (pos ? ib1 : min(k + 1, TVN - 1));
            // Register-selected y values: no load on the chain.
            float ynk  = neg ? yA1 : (pos ? yB1 : yn1);
            float nyn1 = neg ? yA2 : (pos ? yB2 : yn2);
            float nyn2 = y[min(nk + 2, TVN - 1)];   // consumed 2 iters later

            float umin_t = umin + ynk - vmin;
            float umax_t = umax + ynk - vmax;
            bool c1 = (umin_t >= LAM);
            bool c2 = (umax_t <= -LAM);
            float vmin_mid = c1 ? (vmin + (umin_t - LAM) * rc_mid) : vmin;
            float umin_mid = c1 ? LAM : umin_t;
            int   km_mid   = c1 ? nk : km;
            float vmax_mid = c2 ? (vmax + (umax_t + LAM) * rc_mid) : vmax;
            float umax_mid = c2 ? (-LAM) : umax_t;
            int   kp_mid   = c2 ? nk : kp;

            k0 = jump ? nk : k0;
            int   nkm = (neg || mpos) ? nk : (mmid ? km_mid : km);
            int   nkp = (pos || mneg) ? nk : (mmid ? kp_mid : kp);
            float nvmin = neg ? ynk : (mpos ? (ynk - 2.0f * LAM)
                                            : (mmid ? vmin_mid : vmin));
            float nvmax = pos ? ynk : (mneg ? (ynk + 2.0f * LAM)
                                            : (mmid ? vmax_mid : vmax));
            float numin = (neg || mpos) ? LAM
                        : (epos ? (ynk - LAM - vmin)
                                : (mmid ? umin_mid : umin));
            float numax = (pos || mneg) ? (-LAM)
                        : (eneg ? (ynk + LAM - vmax)
                                : (mmid ? umax_mid : umax));

            k = nk; km = nkm; kp = nkp;
            vmin = nvmin; vmax = nvmax; umin = numin; umax = numax;
            yn1 = nyn1; yn2 = nyn2;
        }

        // ---- Branchless expansion of segments into ybuf ----
        float* xr = ybuf + lane * YS;
        int s = 0;
        float v0 = sv[0], v1 = sv[1];
        int   h0 = sh[0], h1 = sh[1];
        for (int i = 0; i < TVN; ++i) {
            bool adv = (i > h0);
            v0 = adv ? v1 : v0;
            h0 = adv ? h1 : h0;
            s += adv;
            xr[i] = v0;
            v1 = sv[s + 1];      // unconditional prefetch, off-chain
            h1 = sh[s + 1];
        }
    }
    __syncwarp();

    // ---- Sparsemax: 4 rows interleaved (4 independent shfl chains) ----
    for (int g = 0; g < RPW; g += 4) {
        float v[4][TVN / 32];
        float mx[4], lo[4], hb[4];
        bool  has[4];
        #pragma unroll
        for (int rr = 0; rr < 4; ++rr) {
            int row = row0 + g + rr;
            has[rr] = (row < nrows);
            const float* z = ybuf + (has[rr] ? (g + rr) : 0) * YS;
            float m = -CUDART_INF_F;
            #pragma unroll
            for (int i = 0; i < TVN / 32; ++i) {
                v[rr][i] = z[lane + 32 * i];
                m = fmaxf(m, v[rr][i]);
            }
            mx[rr] = m;
        }
        #pragma unroll
        for (int o = 16; o; o >>= 1) {
            #pragma unroll
            for (int rr = 0; rr < 4; ++rr)
                mx[rr] = fmaxf(mx[rr], __shfl_xor_sync(0xffffffffu, mx[rr], o));
        }
        #pragma unroll
        for (int rr = 0; rr < 4; ++rr) { lo[rr] = mx[rr] - 1.0f; hb[rr] = mx[rr]; }

        // f(tau) = sum relu(v - tau): f(mx-1) >= 1, f(mx) = 0. Bisect.
        #pragma unroll 1
        for (int it = 0; it < 20; ++it) {
            float sum[4];
            #pragma unroll
            for (int rr = 0; rr < 4; ++rr) {
                float m = 0.5f * (lo[rr] + hb[rr]);
                float s0 = 0.f, s1 = 0.f, s2 = 0.f, s3 = 0.f;
                #pragma unroll
                for (int i = 0; i < TVN / 32; i += 4) {
                    s0 += fmaxf(v[rr][i]     - m, 0.f);
                    s1 += fmaxf(v[rr][i + 1] - m, 0.f);
                    s2 += fmaxf(v[rr][i + 2] - m, 0.f);
                    s3 += fmaxf(v[rr][i + 3] - m, 0.f);
                }
                sum[rr] = (s0 + s1) + (s2 + s3);
            }
            #pragma unroll
            for (int o = 16; o; o >>= 1) {
                #pragma unroll
                for (int rr = 0; rr < 4; ++rr)
                    sum[rr] += __shfl_xor_sync(0xffffffffu, sum[rr], o);
            }
            #pragma unroll
            for (int rr = 0; rr < 4; ++rr) {
                float m = 0.5f * (lo[rr] + hb[rr]);
                if (sum[rr] >= 1.0f) lo[rr] = m; else hb[rr] = m;
            }
        }

        #pragma unroll
        for (int rr = 0; rr < 4; ++rr) {
            if (!has[rr]) continue;
            int row = row0 + g + rr;
            float tau = 0.5f * (lo[rr] + hb[rr]);
            #pragma unroll
            for (int i = 0; i < TVN / 32; ++i)
                out[(size_t)row * TVN + (size_t)(lane + 32 * i)] =
                    fmaxf(v[rr][i] - tau, 0.0f);
        }
    }
}

extern "C" void kernel_launch(void* const* d_in, const int* in_sizes, int n_in,
                              void* d_out, int out_size) {
    const float* x = (const float*)d_in[0];
    float* out = (float*)d_out;
    int nrows = in_sizes[0] / TVN;
    int nblocks = (nrows + RPW - 1) / RPW;
    Fusedmax_fused_kernel<<<nblocks, 32>>>(x, out, nrows);
}

// round 13
// speedup vs baseline: 13.2412x; 1.9934x over previous
#include <cuda_runtime.h>
#include <math_constants.h>

#define TVN  512
#define LAM  1.0f
#define RPW  8            // rows per warp (lanes 0..7 run Condat)
#define YS   516          // ybuf stride: mult of 4, %32==4 -> conflict-free
#define SEGS 520          // segment buffers per row (<=513 used)

__global__ __launch_bounds__(32)
void Fusedmax_fused_kernel(const float* __restrict__ in,
                           float* __restrict__ out, int nrows) {
    __shared__ float          ybuf  [RPW * YS];    // y, then TV result
    __shared__ float          segval[RPW * SEGS];
    __shared__ unsigned short seghi [RPW * SEGS];
    __shared__ float          rcp_tab[TVN + 2];    // rcp_tab[c] = 1/c

    const int lane = threadIdx.x;
    const int row0 = blockIdx.x * RPW;

    for (int i = lane; i < TVN + 2; i += 32)
        rcp_tab[i] = 1.0f / (float)max(i, 1);

    // Cooperative coalesced float4 load of RPW rows.
    for (int i = lane; i < RPW * (TVN / 4); i += 32) {
        int r  = i / (TVN / 4);
        int c4 = i % (TVN / 4);
        int row = row0 + r;
        float4 v = make_float4(0.f, 0.f, 0.f, 0.f);
        if (row < nrows) v = ((const float4*)(in + (size_t)row * TVN))[c4];
        float* dst = ybuf + r * YS + c4 * 4;
        dst[0] = v.x; dst[1] = v.y; dst[2] = v.z; dst[3] = v.w;
    }
    __syncwarp();

    const bool act = (lane < RPW) && (row0 + lane < nrows);
    int cnt = 0;
    if (act) {
        const float*    y  = ybuf   + lane * YS;
        float*          sv = segval + lane * SEGS;
        unsigned short* sh = seghi  + lane * SEGS;

        int k = 0, k0 = 0, km = 0, kp = 0;
        float vmin = y[0] - LAM, vmax = y[0] + LAM;
        float umin = LAM, umax = -LAM;
        float yn1 = y[1];    // y[k+1]
        float yn2 = y[2];    // y[min(k+2, n-1)]

        for (;;) {
            // ---- hot loop: k < n-1, at_end machinery removed ----
            while (k < TVN - 1) {
                // Off-chain loads: all addresses from previous-iter registers.
                // km+1, kp+1 <= k+1 <= n-1 here, so no clamp needed on +1.
                float yA1 = y[km + 1];
                float yA2 = y[min(km + 2, TVN - 1)];
                float yB1 = y[kp + 1];
                float yB2 = y[min(kp + 2, TVN - 1)];
                float rc_mid = rcp_tab[k - k0 + 2];   // 1/(nk-k0+1), mid: nk=k+1

                // Speculative mid-path: consumers only matter when mid,
                // where ynk == yn1 -> computable at cycle 0, off the
                // neg/pos predicate chain.
                float umin_t = umin + yn1 - vmin;
                float umax_t = umax + yn1 - vmax;
                bool  c1 = (umin_t >= LAM);
                bool  c2 = (umax_t <= -LAM);
                float vmin_mid = c1 ? fmaf(umin_t - LAM, rc_mid, vmin) : vmin;
                float vmax_mid = c2 ? fmaf(umax_t + LAM, rc_mid, vmax) : vmax;

                bool neg = (yn1 + umin < vmin - LAM);
                bool pos = (!neg) && (yn1 + umax > vmax + LAM);
                bool ev  = neg | pos;

                // Branchless segment record (stale slot overwritten later).
                sv[cnt] = pos ? vmax : vmin;
                sh[cnt] = (unsigned short)(neg ? km : kp);
                cnt += ev;

                int   nk   = neg ? (km + 1) : (pos ? (kp + 1) : (k + 1));
                float nyn1 = neg ? yA2 : (pos ? yB2 : yn2);
                float nyn2 = y[min(nk + 2, TVN - 1)];

                float jvmin = neg ? yA1 : (yB1 - 2.0f * LAM);
                float jvmax = pos ? yB1 : (yA1 + 2.0f * LAM);

                k0   = ev ? nk : k0;
                km   = (ev | c1) ? nk : km;
                kp   = (ev | c2) ? nk : kp;
                vmin = ev ? jvmin : vmin_mid;
                vmax = ev ? jvmax : vmax_mid;
                umin = (ev | c1) ? LAM    : umin_t;
                umax = (ev | c2) ? (-LAM) : umax_t;
                k = nk; yn1 = nyn1; yn2 = nyn2;
            }

            // ---- end-phase: k == n-1 (rare; faithful at_end step) ----
            bool neg = (umin < 0.0f);
            bool pos = (!neg) && (umax > 0.0f);
            bool fin = (!neg) && (!pos);
            sv[cnt] = pos ? vmax
                          : (fin ? fmaf(umin, rcp_tab[k - k0 + 1], vmin) : vmin);
            sh[cnt] = (unsigned short)(neg ? km : (pos ? kp : (TVN - 1)));
            ++cnt;                               // end-phase always records
            if (fin) break;

            int nk = min(neg ? (km + 1) : (kp + 1), TVN - 1);
            float ynk = y[nk];
            if (neg) {
                km = nk; vmin = ynk; umin = LAM;
                umax = ynk + LAM - vmax;          // eneg
            } else {
                kp = nk; vmax = ynk; umax = -LAM;
                umin = ynk - LAM - vmin;          // epos
            }
            k0 = nk; k = nk;
            yn1 = y[min(nk + 1, TVN - 1)];
            yn2 = y[min(nk + 2, TVN - 1)];
        }
    }
    __syncwarp();

    // ---- Expansion: 4 lanes per row, binary search + 128-wide walk ----
    {
        int myr = lane & 7;
        int q   = lane >> 3;
        int rcnt = __shfl_sync(0xffffffffu, cnt, myr);
        bool rowok = (row0 + myr < nrows) && (rcnt > 0);
        if (rowok) {
            const float*          svr = segval + myr * SEGS;
            const unsigned short* shr = seghi  + myr * SEGS;
            float* xr = ybuf + myr * YS;
            int start = q * (TVN / 4);
            int end   = start + (TVN / 4);
            // first segment s with shr[s] >= start
            int lo = 0, hi = rcnt - 1;
            while (lo < hi) {
                int mid = (lo + hi) >> 1;
                if ((int)shr[mid] < start) lo = mid + 1; else hi = mid;
            }
            int s = lo;
            float v0 = svr[s];     int h0 = shr[s];
            float v1 = svr[s + 1]; int h1 = shr[s + 1];
            for (int i = start; i < end; ++i) {
                bool adv = (i > h0);
                v0 = adv ? v1 : v0;
                h0 = adv ? h1 : h0;
                s += adv;
                xr[i] = v0;
                v1 = svr[s + 1];   // unconditional prefetch, off-chain
                h1 = shr[s + 1];
            }
        }
    }
    __syncwarp();

    // ---- Sparsemax: 4 rows interleaved (4 independent shfl chains) ----
    for (int g = 0; g < RPW; g += 4) {
        float v[4][TVN / 32];
        float mx[4], lo[4], hb[4];
        bool  has[4];
        #pragma unroll
        for (int rr = 0; rr < 4; ++rr) {
            int row = row0 + g + rr;
            has[rr] = (row < nrows);
            const float* z = ybuf + (has[rr] ? (g + rr) : 0) * YS;
            float m = -CUDART_INF_F;
            #pragma unroll
            for (int i = 0; i < TVN / 32; ++i) {
                v[rr][i] = z[lane + 32 * i];
                m = fmaxf(m, v[rr][i]);
            }
            mx[rr] = m;
        }
        #pragma unroll
        for (int o = 16; o; o >>= 1) {
            #pragma unroll
            for (int rr = 0; rr < 4; ++rr)
                mx[rr] = fmaxf(mx[rr], __shfl_xor_sync(0xffffffffu, mx[rr], o));
        }
        #pragma unroll
        for (int rr = 0; rr < 4; ++rr) { lo[rr] = mx[rr] - 1.0f; hb[rr] = mx[rr]; }

        #pragma unroll 1
        for (int it = 0; it < 20; ++it) {
            float sum[4];
            #pragma unroll
            for (int rr = 0; rr < 4; ++rr) {
                float m = 0.5f * (lo[rr] + hb[rr]);
                float s0 = 0.f, s1 = 0.f, s2 = 0.f, s3 = 0.f;
                #pragma unroll
                for (int i = 0; i < TVN / 32; i += 4) {
                    s0 += fmaxf(v[rr][i]     - m, 0.f);
                    s1 += fmaxf(v[rr][i + 1] - m, 0.f);
                    s2 += fmaxf(v[rr][i + 2] - m, 0.f);
                    s3 += fmaxf(v[rr][i + 3] - m, 0.f);
                }
                sum[rr] = (s0 + s1) + (s2 + s3);
            }
            #pragma unroll
            for (int o = 16; o; o >>= 1) {
                #pragma unroll
                for (int rr = 0; rr < 4; ++rr)
                    sum[rr] += __shfl_xor_sync(0xffffffffu, sum[rr], o);
            }
            #pragma unroll
            for (int rr = 0; rr < 4; ++rr) {
                float m = 0.5f * (lo[rr] + hb[rr]);
                if (sum[rr] >= 1.0f) lo[rr] = m; else hb[rr] = m;
            }
        }

        #pragma unroll
        for (int rr = 0; rr < 4; ++rr) {
            if (!has[rr]) continue;
            int row = row0 + g + rr;
            float tau = 0.5f * (lo[rr] + hb[rr]);
            #pragma unroll
            for (int i = 0; i < TVN / 32; ++i)
                out[(size_t)row * TVN + (size_t)(lane + 32 * i)] =
                    fmaxf(v[rr][i] - tau, 0.0f);
        }
    }
}

extern "C" void kernel_launch(void* const* d_in, const int* in_sizes, int n_in,
                              void* d_out, int out_size) {
    const float* x = (const float*)d_in[0];
    float* out = (float*)d_out;
    int nrows = in_sizes[0] / TVN;
    int nblocks = (nrows + RPW - 1) / RPW;
    Fusedmax_fused_kernel<<<nblocks, 32>>>(x, out, nrows);
}

// round 16
// speedup vs baseline: 13.5992x; 1.0270x over previous
#include <cuda_runtime.h>
#include <math_constants.h>

#define TVN  512
#define LAM  1.0f
#define RPW  8            // rows per warp (lanes 0..7 run Condat)
#define YS   516          // ybuf stride: mult of 4, %32==4 -> conflict-free
#define SEGS 520          // segment buffers per row (<=513 used)

__global__ __launch_bounds__(32)
void Fusedmax_fused_kernel(const float* __restrict__ in,
                           float* __restrict__ out, int nrows) {
    __shared__ float          ybuf  [RPW * YS];    // y, then TV result
    __shared__ float          segval[RPW * SEGS];
    __shared__ unsigned short seghi [RPW * SEGS];
    __shared__ float          rcp_tab[TVN + 2];    // rcp_tab[c] = 1/c

    const int lane = threadIdx.x;
    const int row0 = blockIdx.x * RPW;

    for (int i = lane; i < TVN + 2; i += 32)
        rcp_tab[i] = 1.0f / (float)max(i, 1);

    // Cooperative coalesced float4 load of RPW rows.
    for (int i = lane; i < RPW * (TVN / 4); i += 32) {
        int r  = i / (TVN / 4);
        int c4 = i % (TVN / 4);
        int row = row0 + r;
        float4 v = make_float4(0.f, 0.f, 0.f, 0.f);
        if (row < nrows) v = ((const float4*)(in + (size_t)row * TVN))[c4];
        float* dst = ybuf + r * YS + c4 * 4;
        dst[0] = v.x; dst[1] = v.y; dst[2] = v.z; dst[3] = v.w;
    }
    __syncwarp();

    const bool act = (lane < RPW) && (row0 + lane < nrows);
    int cnt = 0;
    if (act) {
        const float*    y  = ybuf   + lane * YS;
        float*          sv = segval + lane * SEGS;
        unsigned short* sh = seghi  + lane * SEGS;

        int k = 0, km = 0, kp = 0, len = 1;      // len = k - k0 + 1
        float vmin = y[0] - LAM, vmax = y[0] + LAM;
        float umin = LAM, umax = -LAM;

        for (;;) {
            // ---- hot loop: k < n-1; lean 1-load-set body ----
            while (k < TVN - 1) {
                // All addresses known at iteration start (prev-iter regs);
                // all indices provably <= TVN-1: no clamps needed.
                float yn1 = y[k + 1];
                float yA1 = y[km + 1];
                float yB1 = y[kp + 1];
                float rc  = rcp_tab[len + 1];     // 1/(nk-k0+1) for mid

                // umin_t = umin + y[k+1] - vmin; predicates collapse onto it:
                //   neg  <=> yn1+umin < vmin-lam <=> umin_t < -lam
                //   pos  <=> yn1+umax > vmax+lam <=> umax_t >  lam
                float umin_t = umin + yn1 - vmin;
                float umax_t = umax + yn1 - vmax;
                bool neg = (umin_t < -LAM);
                bool pos = (!neg) && (umax_t > LAM);
                bool ev  = neg | pos;
                bool c1  = (umin_t >= LAM);
                bool c2  = (umax_t <= -LAM);
                float vmin_mid = c1 ? fmaf(umin_t - LAM, rc, vmin) : vmin;
                float vmax_mid = c2 ? fmaf(umax_t + LAM, rc, vmax) : vmax;

                // Branchless segment record (stale slot overwritten later).
                sv[cnt] = pos ? vmax : vmin;
                sh[cnt] = (unsigned short)(neg ? km : kp);
                cnt += ev;

                int   nk    = neg ? (km + 1) : (pos ? (kp + 1) : (k + 1));
                float jvmin = neg ? yA1 : (yB1 - 2.0f * LAM);
                float jvmax = pos ? yB1 : (yA1 + 2.0f * LAM);

                km   = (ev | c1) ? nk : km;
                kp   = (ev | c2) ? nk : kp;
                vmin = ev ? jvmin : vmin_mid;
                vmax = ev ? jvmax : vmax_mid;
                umin = (ev | c1) ? LAM    : umin_t;
                umax = (ev | c2) ? (-LAM) : umax_t;
                len  = ev ? 1 : (len + 1);
                k = nk;
            }

            // ---- end-phase: k == n-1 (rare; faithful at_end step) ----
            bool neg = (umin < 0.0f);
            bool pos = (!neg) && (umax > 0.0f);
            bool fin = (!neg) && (!pos);
            sv[cnt] = pos ? vmax
                          : (fin ? fmaf(umin, rcp_tab[len], vmin) : vmin);
            sh[cnt] = (unsigned short)(neg ? km : (pos ? kp : (TVN - 1)));
            ++cnt;                               // end-phase always records
            if (fin) break;

            int nk = min(neg ? (km + 1) : (kp + 1), TVN - 1);
            float ynk = y[nk];
            if (neg) {
                km = nk; vmin = ynk; umin = LAM;
                umax = ynk + LAM - vmax;          // eneg
            } else {
                kp = nk; vmax = ynk; umax = -LAM;
                umin = ynk - LAM - vmin;          // epos
            }
            k = nk; len = 1;                      // k0 = nk
        }
    }
    __syncwarp();

    // ---- Expansion: 4 lanes per row, binary search + 128-wide walk ----
    {
        int myr = lane & 7;
        int q   = lane >> 3;
        int rcnt = __shfl_sync(0xffffffffu, cnt, myr);
        bool rowok = (row0 + myr < nrows) && (rcnt > 0);
        if (rowok) {
            const float*          svr = segval + myr * SEGS;
            const unsigned short* shr = seghi  + myr * SEGS;
            float* xr = ybuf + myr * YS;
            int start = q * (TVN / 4);
            int end   = start + (TVN / 4);
            // first segment s with shr[s] >= start
            int lo = 0, hi = rcnt - 1;
            while (lo < hi) {
                int mid = (lo + hi) >> 1;
                if ((int)shr[mid] < start) lo = mid + 1; else hi = mid;
            }
            int s = lo;
            float v0 = svr[s];     int h0 = shr[s];
            float v1 = svr[s + 1]; int h1 = shr[s + 1];
            for (int i = start; i < end; ++i) {
                bool adv = (i > h0);
                v0 = adv ? v1 : v0;
                h0 = adv ? h1 : h0;
                s += adv;
                xr[i] = v0;
                v1 = svr[s + 1];   // unconditional prefetch, off-chain
                h1 = shr[s + 1];
            }
        }
    }
    __syncwarp();

    // ---- Sparsemax: 4 rows interleaved (4 independent shfl chains) ----
    for (int g = 0; g < RPW; g += 4) {
        float v[4][TVN / 32];
        float mx[4], lo[4], hb[4];
        bool  has[4];
        #pragma unroll
        for (int rr = 0; rr < 4; ++rr) {
            int row = row0 + g + rr;
            has[rr] = (row < nrows);
            const float* z = ybuf + (has[rr] ? (g + rr) : 0) * YS;
            float m = -CUDART_INF_F;
            #pragma unroll
            for (int i = 0; i < TVN / 32; ++i) {
                v[rr][i] = z[lane + 32 * i];
                m = fmaxf(m, v[rr][i]);
            }
            mx[rr] = m;
        }
        #pragma unroll
        for (int o = 16; o; o >>= 1) {
            #pragma unroll
            for (int rr = 0; rr < 4; ++rr)
                mx[rr] = fmaxf(mx[rr], __shfl_xor_sync(0xffffffffu, mx[rr], o));
        }
        #pragma unroll
        for (int rr = 0; rr < 4; ++rr) { lo[rr] = mx[rr] - 1.0f; hb[rr] = mx[rr]; }

        // f(tau) = sum relu(v - tau): f(mx-1) >= 1, f(mx) = 0. Bisect.
        #pragma unroll 1
        for (int it = 0; it < 20; ++it) {
            float sum[4];
            #pragma unroll
            for (int rr = 0; rr < 4; ++rr) {
                float m = 0.5f * (lo[rr] + hb[rr]);
                float s0 = 0.f, s1 = 0.f, s2 = 0.f, s3 = 0.f;
                #pragma unroll
                for (int i = 0; i < TVN / 32; i += 4) {
                    s0 += fmaxf(v[rr][i]     - m, 0.f);
                    s1 += fmaxf(v[rr][i + 1] - m, 0.f);
                    s2 += fmaxf(v[rr][i + 2] - m, 0.f);
                    s3 += fmaxf(v[rr][i + 3] - m, 0.f);
                }
                sum[rr] = (s0 + s1) + (s2 + s3);
            }
            #pragma unroll
            for (int o = 16; o; o >>= 1) {
                #pragma unroll
                for (int rr = 0; rr < 4; ++rr)
                    sum[rr] += __shfl_xor_sync(0xffffffffu, sum[rr], o);
            }
            #pragma unroll
            for (int rr = 0; rr < 4; ++rr) {
                float m = 0.5f * (lo[rr] + hb[rr]);
                if (sum[rr] >= 1.0f) lo[rr] = m; else hb[rr] = m;
            }
        }

        #pragma unroll
        for (int rr = 0; rr < 4; ++rr) {
            if (!has[rr]) continue;
            int row = row0 + g + rr;
            float tau = 0.5f * (lo[rr] + hb[rr]);
            #pragma unroll
            for (int i = 0; i < TVN / 32; ++i)
                out[(size_t)row * TVN + (size_t)(lane + 32 * i)] =
                    fmaxf(v[rr][i] - tau, 0.0f);
        }
    }
}

extern "C" void kernel_launch(void* const* d_in, const int* in_sizes, int n_in,
                              void* d_out, int out_size) {
    const float* x = (const float*)d_in[0];
    float* out = (float*)d_out;
    int nrows = in_sizes[0] / TVN;
    int nblocks = (nrows + RPW - 1) / RPW;
    Fusedmax_fused_kernel<<<nblocks, 32>>>(x, out, nrows);
}